// round 10
// baseline (speedup 1.0000x reference)
#include <cuda_runtime.h>
#include <cuda_fp16.h>
#include <math.h>
#include <stdint.h>

// ---------------- static scratch (no allocations allowed) ----------------
__device__ float g_bufA[33554432];   // spike buffers (used as __half)
__device__ float g_bufB[33554432];
__device__ float g_conv[33554432];   // pre-BN conv outputs (fp32)
__device__ float g_wpk[1048576];     // packed weights: halves [0,571392) ; fc1 floats @ +300000
__device__ double g_sum[768];
__device__ double g_sumsq[768];

__device__ __forceinline__ uint32_t smem_u32(const void* p) {
    uint32_t a;
    asm("{ .reg .u64 t; cvta.to.shared.u64 t, %1; cvt.u32.u64 %0, t; }" : "=r"(a) : "l"(p));
    return a;
}
__device__ __forceinline__ void cp_async16(uint32_t dst, const void* src, bool ok) {
    int sz = ok ? 16 : 0;
    asm volatile("cp.async.cg.shared.global [%0], [%1], 16, %2;" :: "r"(dst), "l"(src), "r"(sz));
}
__device__ __forceinline__ void cp_commit() { asm volatile("cp.async.commit_group;"); }
__device__ __forceinline__ void cp_wait2() { asm volatile("cp.async.wait_group 2;"); }
__device__ __forceinline__ void cp_wait1() { asm volatile("cp.async.wait_group 1;"); }
__device__ __forceinline__ void cp_wait0() { asm volatile("cp.async.wait_group 0;"); }
__device__ __forceinline__ void ldsm4(uint32_t& r0, uint32_t& r1, uint32_t& r2, uint32_t& r3, uint32_t addr) {
    asm volatile("ldmatrix.sync.aligned.m8n8.x4.shared.b16 {%0,%1,%2,%3}, [%4];"
                 : "=r"(r0), "=r"(r1), "=r"(r2), "=r"(r3) : "r"(addr));
}
__device__ __forceinline__ int ilog2c(int v) { return (v == 1024) ? 10 : (v == 256) ? 8 : 6; }

// ---------------- prep: zero stats + pack fp16 hi/lo weights + permute fc1 ----------------
// pack layout (halves): [((ch*2+s)*NTILE + j)*32 + lane]*8 + h
// h in 0..7: p=h&3: p<2 -> b0 (k=2t+p), p>=2 -> b1 (k=2t+8+(p-2)); h<4 = hi, h>=4 = lo*2^11
__device__ __forceinline__ void pack_one_h(const float* __restrict__ w, __half* __restrict__ bpk,
                                           int CIN, int COUT, int idx) {
    int h    = idx & 7;
    int r    = idx >> 3;
    int lane = r & 31; r >>= 5;
    int NTILE = COUT / 8;
    int j    = r % NTILE; r /= NTILE;
    int s    = r & 1;
    int ch   = r >> 1;
    int g = lane >> 2, t = lane & 3;
    int CCH = CIN / 32;
    int tap = ch / CCH, c32 = ch % CCH;
    int n = 8 * j + g;
    int p = h & 3;
    int klocal = (p < 2) ? (2 * t + p) : (2 * t + 8 + (p - 2));
    int ci = c32 * 32 + s * 16 + klocal;
    float v = w[((size_t)n * CIN + ci) * 9 + tap];
    __half hi = __float2half_rn(v);
    if (h < 4) bpk[idx] = hi;
    else       bpk[idx] = __float2half_rn((v - __half2float(hi)) * 2048.0f);
}

__global__ void prep_kernel(const float* __restrict__ w2, const float* __restrict__ w3,
                            const float* __restrict__ w4, const float* __restrict__ w5,
                            const float* __restrict__ w6, const float* __restrict__ fc1w,
                            float* __restrict__ wpk, double* __restrict__ sum, double* __restrict__ sumsq)
{
    __half* hk = (__half*)wpk;
    int idx = blockIdx.x * 256 + threadIdx.x;
    if (idx < 768) { sum[idx] = 0.0; sumsq[idx] = 0.0; }
    if (idx < 18432)        pack_one_h(w2, hk,          32,  32, idx);
    else if (idx < 55296)   pack_one_h(w3, hk + 18432,  32,  64, idx - 18432);
    else if (idx < 129024)  pack_one_h(w4, hk + 55296,  64,  64, idx - 55296);
    else if (idx < 276480)  pack_one_h(w5, hk + 129024, 64, 128, idx - 129024);
    else if (idx < 571392)  pack_one_h(w6, hk + 276480, 128, 128, idx - 276480);
    else if (idx < 833536) {
        int i = idx - 571392;                // fc1: NCHW-flatten -> NHWC-flatten
        int o = i / 2048, k = i % 2048;      // k = yx*128 + c
        int c = k % 128, yx = k / 128;
        wpk[300000 + i] = fc1w[o * 2048 + c * 16 + yx];
    }
}

// ---------------- fp16 m16n8k16 implicit GEMM 3x3 conv (NHWC), 3-stage cp.async + ldmatrix ----------------
// Warp grid WM x WN; each warp: 2 m16 strips (M_w=32), NT = COUT/8/WN n8-tiles.
// A in smem fp16, 40-half (80B) pixel stride (conflict-free for ldmatrix).
template<int CIN, int COUT, int H, int W, int WM, int WN>
__global__ __launch_bounds__(256, 3) void conv_mma(const __half* __restrict__ in,
                                                   const __half* __restrict__ bpk,
                                                   const float* __restrict__ bias,
                                                   float* __restrict__ out,
                                                   double* __restrict__ dsum,
                                                   double* __restrict__ dsumsq)
{
    constexpr int HW = H * W;
    constexpr int LHW = (HW == 1024) ? 10 : (HW == 256) ? 8 : 6;
    constexpr int LW  = (W == 32) ? 5 : (W == 16) ? 4 : 3;
    constexpr int CCH = CIN / 32;
    constexpr int NCH = 9 * CCH;
    constexpr int PX = WM * 32;
    constexpr int NTILE = COUT / 8;
    constexpr int NT = NTILE / WN;
    constexpr uint32_t A_BYTES = PX * 80;          // 40 halves per pixel
    constexpr uint32_t B_BYTES = 128 * COUT;       // hi+lo, 32 k-halves
    constexpr int NA = PX * 4 / 256;               // A cp.asyncs per thread
    constexpr int NB = (B_BYTES / 16) / 256;       // B cp.asyncs per thread

    extern __shared__ char smem[];
    float* Ss = (float*)(smem + 3 * A_BYTES + 3 * B_BYTES);   // [2*COUT]
    const uint32_t sA = smem_u32(smem);
    const uint32_t sB = sA + 3 * A_BYTES;

    const int tid  = threadIdx.x;
    const int wid  = tid >> 5;
    const int lane = tid & 31;
    const int g = lane >> 2, t = lane & 3;
    const int wm = wid % WM, wn = wid / WM;
    const int p0 = blockIdx.x * PX;

    if (tid < 2 * COUT) Ss[tid] = 0.f;

    // issue a chunk's A (im2col gather, coords recomputed: shifts only) + B (linear)
    auto issue = [&](int ch, int buf) {
        int tap = ch / CCH, c32 = ch % CCH;
        int ky = tap / 3 - 1, kx = tap % 3 - 1;
        uint32_t ab = sA + (uint32_t)buf * A_BYTES;
        const int j4 = tid & 3;
        #pragma unroll
        for (int it = 0; it < NA; it++) {
            int lin = it * 256 + tid;
            int ml = lin >> 2;
            int P = p0 + ml;
            int img = P >> LHW, pix = P & (HW - 1);
            int yy = (pix >> LW) + ky, xx = (pix & (W - 1)) + kx;
            bool ok = ((unsigned)yy < (unsigned)H) && ((unsigned)xx < (unsigned)W);
            const __half* gp = in + (size_t)img * HW * CIN + j4 * 8
                             + (ok ? ((size_t)((yy << LW) + xx) * CIN + c32 * 32) : 0);
            cp_async16(ab + (uint32_t)(ml * 80 + j4 * 16), gp, ok);
        }
        const uint4* src = (const uint4*)(bpk + (size_t)ch * (B_BYTES / 2));
        uint32_t bb = sB + (uint32_t)buf * B_BYTES;
        #pragma unroll
        for (int i = 0; i < NB; i++) {
            int e = i * 256 + tid;
            cp_async16(bb + (uint32_t)e * 16, src + e, true);
        }
        cp_commit();
    };

    float accH[NT][2][4], accL[NT][2][4];
    #pragma unroll
    for (int j = 0; j < NT; j++)
        #pragma unroll
        for (int ms = 0; ms < 2; ms++)
            #pragma unroll
            for (int q = 0; q < 4; q++) { accH[j][ms][q] = 0.f; accL[j][ms][q] = 0.f; }

    issue(0, 0);
    if (NCH > 1) issue(1, 1);

    // ldmatrix lane addressing (within A buffer):
    const int m0 = wm * 32;
    const uint32_t lrow = (uint32_t)(m0 + (lane & 7) + (((lane >> 3) & 1) << 3));
    const uint32_t lkoff = (uint32_t)((lane >> 4) << 4);

    for (int ch = 0; ch < NCH; ch++) {
        int buf = ch % 3;
        if (ch + 2 < NCH)      { issue(ch + 2, (ch + 2) % 3); cp_wait2(); }
        else if (ch + 1 < NCH) { cp_wait1(); }
        else                   { cp_wait0(); }
        __syncthreads();

        const uint32_t abase = sA + (uint32_t)buf * A_BYTES;
        const uint4* Bs4 = (const uint4*)(smem + 3 * A_BYTES + (uint32_t)buf * B_BYTES);
        #pragma unroll
        for (int s = 0; s < 2; s++) {
            uint32_t a[2][4];
            #pragma unroll
            for (int ms = 0; ms < 2; ms++) {
                uint32_t addr = abase + (lrow + ms * 16) * 80 + s * 32 + lkoff;
                ldsm4(a[ms][0], a[ms][1], a[ms][2], a[ms][3], addr);
            }
            #pragma unroll
            for (int j = 0; j < NT; j++) {
                int jg = wn * NT + j;
                uint4 bf = Bs4[(s * NTILE + jg) * 32 + lane];
                #pragma unroll
                for (int ms = 0; ms < 2; ms++) {
                    asm("mma.sync.aligned.m16n8k16.row.col.f32.f16.f16.f32 "
                        "{%0,%1,%2,%3}, {%4,%5,%6,%7}, {%8,%9}, {%0,%1,%2,%3};"
                        : "+f"(accH[j][ms][0]), "+f"(accH[j][ms][1]), "+f"(accH[j][ms][2]), "+f"(accH[j][ms][3])
                        : "r"(a[ms][0]), "r"(a[ms][1]), "r"(a[ms][2]), "r"(a[ms][3]), "r"(bf.x), "r"(bf.y));
                    asm("mma.sync.aligned.m16n8k16.row.col.f32.f16.f16.f32 "
                        "{%0,%1,%2,%3}, {%4,%5,%6,%7}, {%8,%9}, {%0,%1,%2,%3};"
                        : "+f"(accL[j][ms][0]), "+f"(accL[j][ms][1]), "+f"(accL[j][ms][2]), "+f"(accL[j][ms][3])
                        : "r"(a[ms][0]), "r"(a[ms][1]), "r"(a[ms][2]), "r"(a[ms][3]), "r"(bf.z), "r"(bf.w));
                }
            }
        }
        __syncthreads();
    }

    // ---- epilogue: combine hi + lo*2^-11, bias, store (NHWC), fused BN stats ----
    const float LS = 1.0f / 2048.0f;
    #pragma unroll
    for (int j = 0; j < NT; j++) {
        int col = (wn * NT + j) * 8 + 2 * t;
        float2 bb = *(const float2*)&bias[col];
        float s0 = 0.f, s1 = 0.f, q0 = 0.f, q1 = 0.f;
        #pragma unroll
        for (int ms = 0; ms < 2; ms++) {
            int row0 = p0 + m0 + ms * 16 + g;
            float2 v0 = make_float2(accH[j][ms][0] + accL[j][ms][0] * LS + bb.x,
                                    accH[j][ms][1] + accL[j][ms][1] * LS + bb.y);
            float2 v1 = make_float2(accH[j][ms][2] + accL[j][ms][2] * LS + bb.x,
                                    accH[j][ms][3] + accL[j][ms][3] * LS + bb.y);
            *(float2*)&out[(size_t)row0 * COUT + col] = v0;
            *(float2*)&out[(size_t)(row0 + 8) * COUT + col] = v1;
            s0 += v0.x + v1.x; s1 += v0.y + v1.y;
            q0 += v0.x * v0.x + v1.x * v1.x;
            q1 += v0.y * v0.y + v1.y * v1.y;
        }
        #pragma unroll
        for (int off = 4; off < 32; off <<= 1) {
            s0 += __shfl_xor_sync(0xffffffffu, s0, off);
            s1 += __shfl_xor_sync(0xffffffffu, s1, off);
            q0 += __shfl_xor_sync(0xffffffffu, q0, off);
            q1 += __shfl_xor_sync(0xffffffffu, q1, off);
        }
        if (g == 0) {
            atomicAdd(&Ss[col], s0);
            atomicAdd(&Ss[col + 1], s1);
            atomicAdd(&Ss[COUT + col], q0);
            atomicAdd(&Ss[COUT + col + 1], q1);
        }
    }
    __syncthreads();
    if (tid < COUT) {
        atomicAdd(&dsum[tid], (double)Ss[tid]);
        atomicAdd(&dsumsq[tid], (double)Ss[COUT + tid]);
    }
}

// ---------------- layer-1 direct fp32 conv (CIN=3), NCHW in -> NHWC out, fused BN stats ----------------
template<int CIN, int COUT, int H, int W, int RPB, int CO_BLK, int CCH, int NT>
__global__ __launch_bounds__(NT) void conv3x3_kernel(
    const float* __restrict__ in, const float* __restrict__ wgt,
    const float* __restrict__ bias, float* __restrict__ out,
    double* __restrict__ dsum, double* __restrict__ dsumsq)
{
    constexpr int TH = RPB + 2, TW = W + 2;
    constexpr int IN_FLOATS = CCH * TH * TW;
    constexpr int W_FLOATS = CCH * 9 * CO_BLK;
    constexpr int NCG = CO_BLK / 8;
    extern __shared__ float smemf[];
    float* s_in = smemf;
    float* s_w  = smemf + IN_FLOATS;
    float* Ss   = smemf + IN_FLOATS + W_FLOATS;

    const int m = blockIdx.x;
    const int row0 = blockIdx.y * RPB;
    const int cobase = blockIdx.z * CO_BLK;
    const int tid = threadIdx.x;
    const int lane = tid & 31;
    const int cg = tid % NCG;
    const int pg = tid / NCG;
    const int r = pg / (W / 4);
    const int c0 = (pg % (W / 4)) * 4;

    if (tid < 2 * COUT) Ss[tid] = 0.f;

    float acc[4][8];
    #pragma unroll
    for (int p = 0; p < 4; p++)
        #pragma unroll
        for (int q = 0; q < 8; q++) acc[p][q] = 0.f;

    for (int cb = 0; cb < CIN; cb += CCH) {
        for (int e = tid; e < IN_FLOATS; e += NT) {
            int ci = e / (TH * TW); int rem = e % (TH * TW);
            int rr = rem / TW, cc = rem % TW;
            int gr = row0 - 1 + rr, gc = cc - 1;
            float v = 0.f;
            if (gr >= 0 && gr < H && gc >= 0 && gc < W)
                v = in[(((size_t)m * CIN + cb + ci) * H + gr) * W + gc];
            s_in[e] = v;
        }
        for (int e = tid; e < W_FLOATS; e += NT) {
            int co = e % CO_BLK; int t9 = (e / CO_BLK) % 9; int ci = e / (9 * CO_BLK);
            s_w[e] = wgt[(((size_t)(cobase + co)) * CIN + cb + ci) * 9 + t9];
        }
        __syncthreads();

        for (int ci = 0; ci < CCH; ci++) {
            const float* tin = s_in + ci * TH * TW;
            const float* tw  = s_w  + ci * 9 * CO_BLK + cg * 8;
            #pragma unroll
            for (int kh = 0; kh < 3; kh++) {
                float xv[6];
                const float* rowp = tin + (r + kh) * TW + c0;
                #pragma unroll
                for (int j = 0; j < 6; j++) xv[j] = rowp[j];
                #pragma unroll
                for (int kw = 0; kw < 3; kw++) {
                    const float4 w0 = *(const float4*)(tw + (kh * 3 + kw) * CO_BLK);
                    const float4 w1 = *(const float4*)(tw + (kh * 3 + kw) * CO_BLK + 4);
                    float wv[8] = {w0.x, w0.y, w0.z, w0.w, w1.x, w1.y, w1.z, w1.w};
                    #pragma unroll
                    for (int p = 0; p < 4; p++)
                        #pragma unroll
                        for (int q = 0; q < 8; q++)
                            acc[p][q] += xv[kw + p] * wv[q];
                }
            }
        }
        __syncthreads();
    }

    float bq[8];
    #pragma unroll
    for (int q = 0; q < 8; q++) bq[q] = bias[cobase + cg * 8 + q];
    float ssum[8], ssq[8];
    #pragma unroll
    for (int q = 0; q < 8; q++) { ssum[q] = 0.f; ssq[q] = 0.f; }
    #pragma unroll
    for (int p = 0; p < 4; p++) {
        float v[8];
        #pragma unroll
        for (int q = 0; q < 8; q++) {
            v[q] = acc[p][q] + bq[q];
            ssum[q] += v[q];
            ssq[q]  += v[q] * v[q];
        }
        float* op = &out[(((size_t)m * H + row0 + r) * W + c0 + p) * COUT + cobase + cg * 8];
        *(float4*)op       = make_float4(v[0], v[1], v[2], v[3]);
        *(float4*)(op + 4) = make_float4(v[4], v[5], v[6], v[7]);
    }
    #pragma unroll
    for (int off = 4; off < 32; off <<= 1)
        #pragma unroll
        for (int q = 0; q < 8; q++) {
            ssum[q] += __shfl_xor_sync(0xffffffffu, ssum[q], off);
            ssq[q]  += __shfl_xor_sync(0xffffffffu, ssq[q], off);
        }
    if (lane < 4) {
        #pragma unroll
        for (int q = 0; q < 8; q++) {
            int chn = cobase + lane * 8 + q;
            atomicAdd(&Ss[chn], ssum[q]);
            atomicAdd(&Ss[COUT + chn], ssq[q]);
        }
    }
    __syncthreads();
    if (tid < COUT) {
        atomicAdd(&dsum[tid], (double)Ss[tid]);
        atomicAdd(&dsumsq[tid], (double)Ss[COUT + tid]);
    }
}

// ---------------- inline BN finalize helper ----------------
__device__ __forceinline__ void bn_coeffs(const double* sum, const double* sumsq, double icnt,
                                          const float* gam, const float* bet, int c,
                                          float& iv, float& sh)
{
    double mu = sum[c] * icnt;
    double var = sumsq[c] * icnt - mu * mu;
    iv = gam[c] / sqrtf((float)var + 1e-5f);
    sh = bet[c] - (float)mu * iv;
}

// ---------------- LIF (TAU=2, th=1, hard reset), NHWC, fp16 spikes out ----------------
__global__ void lif_seq_kernel(const float* __restrict__ x, __half* __restrict__ s,
                               const double* __restrict__ sum, const double* __restrict__ sumsq,
                               double icnt, const float* __restrict__ gam, const float* __restrict__ bet,
                               int nsite, int C)
{
    int idx = blockIdx.x * blockDim.x + threadIdx.x;
    if (idx >= nsite) return;
    float iv = 1.f, sh = 0.f;
    if (gam) bn_coeffs(sum, sumsq, icnt, gam, bet, idx % C, iv, sh);
    float v = 0.f;
    #pragma unroll
    for (int t = 0; t < 8; t++) {
        float y = x[(size_t)t * nsite + idx] * iv + sh;
        v = 0.5f * (v + y);
        float sp = (v >= 1.0f) ? 1.0f : 0.0f;
        s[(size_t)t * nsite + idx] = __float2half(sp);
        v *= (1.0f - sp);
    }
}

// Layer-1 LIF: input identical across T (read once)
__global__ void lif_bcast_kernel(const float* __restrict__ x, __half* __restrict__ s,
                                 const double* __restrict__ sum, const double* __restrict__ sumsq,
                                 double icnt, const float* __restrict__ gam, const float* __restrict__ bet,
                                 int nsite, int C)
{
    int idx = blockIdx.x * blockDim.x + threadIdx.x;
    if (idx >= nsite) return;
    float iv, sh;
    bn_coeffs(sum, sumsq, icnt, gam, bet, idx % C, iv, sh);
    float y = x[idx] * iv + sh;
    float v = 0.f;
    #pragma unroll
    for (int t = 0; t < 8; t++) {
        v = 0.5f * (v + y);
        float sp = (v >= 1.0f) ? 1.0f : 0.0f;
        s[(size_t)t * nsite + idx] = __float2half(sp);
        v *= (1.0f - sp);
    }
}

// ---------------- LIF + 2x2 maxpool fused, fp16 spikes out ----------------
__global__ void lif_pool_kernel(const float* __restrict__ x, __half* __restrict__ s,
                                const double* __restrict__ sum, const double* __restrict__ sumsq,
                                double icnt, const float* __restrict__ gam, const float* __restrict__ bet,
                                int nout, int C, int OH, int OW, int Nimg)
{
    int idx = blockIdx.x * blockDim.x + threadIdx.x;
    if (idx >= nout) return;
    int c = idx % C;
    int r = idx / C;
    int ox = r % OW; r /= OW;
    int oy = r % OH;
    int n = r / OH;
    float iv, sh;
    bn_coeffs(sum, sumsq, icnt, gam, bet, c, iv, sh);
    int Wi = OW * 2, Hi = OH * 2;
    size_t base = (((size_t)n * Hi + 2 * oy) * Wi + 2 * ox) * C + c;
    size_t tstr = (size_t)Nimg * Hi * Wi * C;
    size_t rstr = (size_t)Wi * C;
    float v0 = 0.f, v1 = 0.f, v2 = 0.f, v3 = 0.f;
    #pragma unroll
    for (int t = 0; t < 8; t++) {
        const float* p = x + (size_t)t * tstr + base;
        float y0 = p[0] * iv + sh;
        float y1 = p[C] * iv + sh;
        float y2 = p[rstr] * iv + sh;
        float y3 = p[rstr + C] * iv + sh;
        v0 = 0.5f * (v0 + y0); float s0 = (v0 >= 1.0f) ? 1.0f : 0.0f; v0 *= (1.0f - s0);
        v1 = 0.5f * (v1 + y1); float s1 = (v1 >= 1.0f) ? 1.0f : 0.0f; v1 *= (1.0f - s1);
        v2 = 0.5f * (v2 + y2); float s2 = (v2 >= 1.0f) ? 1.0f : 0.0f; v2 *= (1.0f - s2);
        v3 = 0.5f * (v3 + y3); float s3 = (v3 >= 1.0f) ? 1.0f : 0.0f; v3 *= (1.0f - s3);
        s[(size_t)t * nout + idx] = __float2half(fmaxf(fmaxf(s0, s1), fmaxf(s2, s3)));
    }
}

// ---------------- fc1: [1024,2048](fp16 spikes) x [128,2048]^T + bias ----------------
__global__ __launch_bounds__(256) void fc1_kernel(const __half* __restrict__ A,
                                                  const float* __restrict__ Bw,
                                                  const float* __restrict__ bias,
                                                  float* __restrict__ C)
{
    __shared__ float As[32][64];
    __shared__ float Bs[64][132];
    int tid = threadIdx.x;
    int r0 = blockIdx.x * 32;
    int tx = tid % 32, ty = tid / 32;
    float acc[4][4];
    #pragma unroll
    for (int i = 0; i < 4; i++)
        #pragma unroll
        for (int j = 0; j < 4; j++) acc[i][j] = 0.f;

    for (int k0 = 0; k0 < 2048; k0 += 64) {
        #pragma unroll
        for (int l = 0; l < 8; l++) {
            int e = tid + l * 256;
            int rr = e >> 6, kk = e & 63;
            As[rr][kk] = __half2float(A[(size_t)(r0 + rr) * 2048 + k0 + kk]);
        }
        #pragma unroll
        for (int l = 0; l < 32; l++) {
            int e = tid + l * 256;
            int kk = e & 63, oo = e >> 6;
            Bs[kk][oo] = Bw[(size_t)oo * 2048 + k0 + kk];
        }
        __syncthreads();
        for (int kk = 0; kk < 64; kk++) {
            float a[4];
            #pragma unroll
            for (int i = 0; i < 4; i++) a[i] = As[ty * 4 + i][kk];
            float4 bv = *(const float4*)&Bs[kk][tx * 4];
            float b[4] = {bv.x, bv.y, bv.z, bv.w};
            #pragma unroll
            for (int i = 0; i < 4; i++)
                #pragma unroll
                for (int j = 0; j < 4; j++)
                    acc[i][j] += a[i] * b[j];
        }
        __syncthreads();
    }
    #pragma unroll
    for (int i = 0; i < 4; i++)
        #pragma unroll
        for (int j = 0; j < 4; j++)
            C[(size_t)(r0 + ty * 4 + i) * 128 + tx * 4 + j] = acc[i][j] + bias[tx * 4 + j];
}

// ---------------- fc2 + LIF + mean over T, fused (fp16 h) ----------------
__global__ __launch_bounds__(320) void fc2_lif_mean_kernel(const __half* __restrict__ h,
                                                           const float* __restrict__ w2,
                                                           const float* __restrict__ b2,
                                                           float* __restrict__ out)
{
    int n = blockIdx.x;
    int o = threadIdx.x / 32;
    int lane = threadIdx.x % 32;
    float w[4];
    #pragma unroll
    for (int j = 0; j < 4; j++) w[j] = w2[o * 128 + lane * 4 + j];
    float bb = b2[o];
    float v = 0.f, accum = 0.f;
    #pragma unroll
    for (int t = 0; t < 8; t++) {
        const __half* hp = h + (size_t)t * 16384 + (size_t)n * 128 + lane * 4;
        float p = 0.f;
        #pragma unroll
        for (int j = 0; j < 4; j++) p += __half2float(hp[j]) * w[j];
        #pragma unroll
        for (int off = 16; off > 0; off >>= 1)
            p += __shfl_xor_sync(0xffffffffu, p, off);
        float y = p + bb;
        v = 0.5f * (v + y);
        float sp = (v >= 1.0f) ? 1.0f : 0.0f;
        v *= (1.0f - sp);
        accum += sp;
    }
    if (lane == 0) out[n * 10 + o] = accum * 0.125f;
}

// ---------------- host orchestration ----------------
extern "C" void kernel_launch(void* const* d_in, const int* in_sizes, int n_in,
                              void* d_out, int out_size)
{
    const float* x = (const float*)d_in[0];
    const float* w[6]; const float* b[6]; const float* gm[6]; const float* be[6];
    for (int i = 0; i < 6; i++) {
        w[i]  = (const float*)d_in[1 + 4 * i];
        b[i]  = (const float*)d_in[2 + 4 * i];
        gm[i] = (const float*)d_in[3 + 4 * i];
        be[i] = (const float*)d_in[4 + 4 * i];
    }
    const float* fc1_w = (const float*)d_in[25];
    const float* fc1_b = (const float*)d_in[26];
    const float* fc2_w = (const float*)d_in[27];
    const float* fc2_b = (const float*)d_in[28];
    float* out = (float*)d_out;

    float *bufA_f, *bufB_f, *conv, *wpk;
    double *sum, *sumsq;
    cudaGetSymbolAddress((void**)&bufA_f, g_bufA);
    cudaGetSymbolAddress((void**)&bufB_f, g_bufB);
    cudaGetSymbolAddress((void**)&conv, g_conv);
    cudaGetSymbolAddress((void**)&wpk, g_wpk);
    cudaGetSymbolAddress((void**)&sum, g_sum);
    cudaGetSymbolAddress((void**)&sumsq, g_sumsq);
    __half* bufA = (__half*)bufA_f;
    __half* bufB = (__half*)bufB_f;

    __half* hk = (__half*)wpk;
    __half* wp2 = hk;             // halves
    __half* wp3 = hk + 18432;
    __half* wp4 = hk + 55296;
    __half* wp5 = hk + 129024;
    __half* wp6 = hk + 276480;
    float*  wfc = wpk + 300000;   // floats

    auto k1 = conv3x3_kernel<3, 32, 32, 32, 8, 32, 3, 256>;
    const int sm1 = (3 * 10 * 34 + 3 * 9 * 32 + 64) * 4;

    auto g2 = conv_mma<32, 32, 32, 32, 4, 2>;      // PX=128, NT=2
    auto g3 = conv_mma<32, 64, 16, 16, 4, 2>;      // PX=128, NT=4
    auto g4 = conv_mma<64, 64, 16, 16, 4, 2>;
    auto g5 = conv_mma<64, 128, 8, 8, 2, 4>;       // PX=64, NT=4
    auto g6 = conv_mma<128, 128, 8, 8, 2, 4>;
    const int smg2  = 3 * 128 * 80 + 3 * 128 * 32 + 64 * 4;     // 43264
    const int smg34 = 3 * 128 * 80 + 3 * 128 * 64 + 128 * 4;    // 55808
    const int smg56 = 3 * 64 * 80 + 3 * 128 * 128 + 256 * 4;    // 65536
    cudaFuncSetAttribute((const void*)g2, cudaFuncAttributeMaxDynamicSharedMemorySize, smg2);
    cudaFuncSetAttribute((const void*)g3, cudaFuncAttributeMaxDynamicSharedMemorySize, smg34);
    cudaFuncSetAttribute((const void*)g4, cudaFuncAttributeMaxDynamicSharedMemorySize, smg34);
    cudaFuncSetAttribute((const void*)g5, cudaFuncAttributeMaxDynamicSharedMemorySize, smg56);
    cudaFuncSetAttribute((const void*)g6, cudaFuncAttributeMaxDynamicSharedMemorySize, smg56);

    const int N = 128, M = 1024;  // M = T*N
    double* s1 = sum;        double* q1 = sumsq;
    double* s2 = sum + 128;  double* q2 = sumsq + 128;
    double* s3 = sum + 256;  double* q3 = sumsq + 256;
    double* s4 = sum + 384;  double* q4 = sumsq + 384;
    double* s5 = sum + 512;  double* q5 = sumsq + 512;
    double* s6 = sum + 640;  double* q6 = sumsq + 640;

    // launch 0: prep
    prep_kernel<<<3257, 256>>>(w[1], w[2], w[3], w[4], w[5], fc1_w, wpk, sum, sumsq);
    // launch 1: layer-1 conv + fused BN stats
    k1<<<dim3(N, 4, 1), 256, sm1>>>(x, w[0], b[0], conv, s1, q1);
    // launch 2: layer-1 LIF (broadcast over T)
    {
        int nsite = N * 1024 * 32;
        lif_bcast_kernel<<<(nsite + 255) / 256, 256>>>(conv, bufA, s1, q1,
            1.0 / ((double)N * 1024), gm[0], be[0], nsite, 32);
    }
    // launch 3: layer-2 conv  <-- ncu capture target
    g2<<<M * 1024 / 128, 256, smg2>>>(bufA, wp2, b[1], conv, s2, q2);
    {
        int nout = N * 16 * 16 * 32;
        lif_pool_kernel<<<(nout + 255) / 256, 256>>>(conv, bufB, s2, q2,
            1.0 / ((double)M * 1024), gm[1], be[1], nout, 32, 16, 16, N);
    }
    // layer 3
    g3<<<M * 256 / 128, 256, smg34>>>(bufB, wp3, b[2], conv, s3, q3);
    {
        int nsite = N * 256 * 64;
        lif_seq_kernel<<<(nsite + 255) / 256, 256>>>(conv, bufA, s3, q3,
            1.0 / ((double)M * 256), gm[2], be[2], nsite, 64);
    }
    // layer 4 (+pool)
    g4<<<M * 256 / 128, 256, smg34>>>(bufA, wp4, b[3], conv, s4, q4);
    {
        int nout = N * 8 * 8 * 64;
        lif_pool_kernel<<<(nout + 255) / 256, 256>>>(conv, bufB, s4, q4,
            1.0 / ((double)M * 256), gm[3], be[3], nout, 64, 8, 8, N);
    }
    // layer 5
    g5<<<M * 64 / 64, 256, smg56>>>(bufB, wp5, b[4], conv, s5, q5);
    {
        int nsite = N * 64 * 128;
        lif_seq_kernel<<<(nsite + 255) / 256, 256>>>(conv, bufA, s5, q5,
            1.0 / ((double)M * 64), gm[4], be[4], nsite, 128);
    }
    // layer 6 (+pool)
    g6<<<M * 64 / 64, 256, smg56>>>(bufA, wp6, b[5], conv, s6, q6);
    {
        int nout = N * 4 * 4 * 128;
        lif_pool_kernel<<<(nout + 255) / 256, 256>>>(conv, bufB, s6, q6,
            1.0 / ((double)M * 64), gm[5], be[5], nout, 128, 4, 4, N);
    }
    // fc1 + LIF
    fc1_kernel<<<32, 256>>>(bufB, wfc, fc1_b, conv);
    {
        int nsite = N * 128;
        lif_seq_kernel<<<(nsite + 255) / 256, 256>>>(conv, bufA, (const double*)0, (const double*)0,
            0.0, (const float*)0, (const float*)0, nsite, 1);
    }
    // fc2 + LIF + mean
    fc2_lif_mean_kernel<<<N, 320>>>(bufA, fc2_w, fc2_b, out);
}

// round 11
// speedup vs baseline: 1.2627x; 1.2627x over previous
#include <cuda_runtime.h>
#include <cuda_fp16.h>
#include <math.h>
#include <stdint.h>

// ---------------- static scratch (no allocations allowed) ----------------
__device__ float g_bufA[33554432];   // spike buffers (used as __half)
__device__ float g_bufB[33554432];
__device__ float g_conv[33554432];   // pre-BN conv outputs (fp32)
__device__ float g_wpk[1048576];     // packed weights: halves [0,571392) ; fc1 floats @ +300000
__device__ double g_sum[768];
__device__ double g_sumsq[768];

__device__ __forceinline__ uint32_t smem_u32(const void* p) {
    uint32_t a;
    asm("{ .reg .u64 t; cvta.to.shared.u64 t, %1; cvt.u32.u64 %0, t; }" : "=r"(a) : "l"(p));
    return a;
}
__device__ __forceinline__ void cp_async16(uint32_t dst, const void* src, bool ok) {
    int sz = ok ? 16 : 0;
    asm volatile("cp.async.cg.shared.global [%0], [%1], 16, %2;" :: "r"(dst), "l"(src), "r"(sz));
}
__device__ __forceinline__ void cp_commit() { asm volatile("cp.async.commit_group;"); }
__device__ __forceinline__ void cp_wait2() { asm volatile("cp.async.wait_group 2;"); }
__device__ __forceinline__ void cp_wait1() { asm volatile("cp.async.wait_group 1;"); }
__device__ __forceinline__ void cp_wait0() { asm volatile("cp.async.wait_group 0;"); }
__device__ __forceinline__ void ldsm4(uint32_t& r0, uint32_t& r1, uint32_t& r2, uint32_t& r3, uint32_t addr) {
    asm volatile("ldmatrix.sync.aligned.m8n8.x4.shared.b16 {%0,%1,%2,%3}, [%4];"
                 : "=r"(r0), "=r"(r1), "=r"(r2), "=r"(r3) : "r"(addr));
}

// ---------------- prep: zero stats + pack fp16 hi/lo weights + permute fc1 ----------------
// pack layout (halves): [((ch*2+s)*NTILE + j)*32 + lane]*8 + h
// h in 0..7: p=h&3: p<2 -> b0 (k=2t+p), p>=2 -> b1 (k=2t+8+(p-2)); h<4 = hi, h>=4 = lo*2^11
__device__ __forceinline__ void pack_one_h(const float* __restrict__ w, __half* __restrict__ bpk,
                                           int CIN, int COUT, int idx) {
    int h    = idx & 7;
    int r    = idx >> 3;
    int lane = r & 31; r >>= 5;
    int NTILE = COUT / 8;
    int j    = r % NTILE; r /= NTILE;
    int s    = r & 1;
    int ch   = r >> 1;
    int g = lane >> 2, t = lane & 3;
    int CCH = CIN / 32;
    int tap = ch / CCH, c32 = ch % CCH;
    int n = 8 * j + g;
    int p = h & 3;
    int klocal = (p < 2) ? (2 * t + p) : (2 * t + 8 + (p - 2));
    int ci = c32 * 32 + s * 16 + klocal;
    float v = w[((size_t)n * CIN + ci) * 9 + tap];
    __half hi = __float2half_rn(v);
    if (h < 4) bpk[idx] = hi;
    else       bpk[idx] = __float2half_rn((v - __half2float(hi)) * 2048.0f);
}

__global__ void prep_kernel(const float* __restrict__ w2, const float* __restrict__ w3,
                            const float* __restrict__ w4, const float* __restrict__ w5,
                            const float* __restrict__ w6, const float* __restrict__ fc1w,
                            float* __restrict__ wpk, double* __restrict__ sum, double* __restrict__ sumsq)
{
    __half* hk = (__half*)wpk;
    int idx = blockIdx.x * 256 + threadIdx.x;
    if (idx < 768) { sum[idx] = 0.0; sumsq[idx] = 0.0; }
    if (idx < 18432)        pack_one_h(w2, hk,          32,  32, idx);
    else if (idx < 55296)   pack_one_h(w3, hk + 18432,  32,  64, idx - 18432);
    else if (idx < 129024)  pack_one_h(w4, hk + 55296,  64,  64, idx - 55296);
    else if (idx < 276480)  pack_one_h(w5, hk + 129024, 64, 128, idx - 129024);
    else if (idx < 571392)  pack_one_h(w6, hk + 276480, 128, 128, idx - 276480);
    else if (idx < 833536) {
        int i = idx - 571392;                // fc1: NCHW-flatten -> NHWC-flatten
        int o = i / 2048, k = i % 2048;      // k = yx*128 + c
        int c = k % 128, yx = k / 128;
        wpk[300000 + i] = fc1w[o * 2048 + c * 16 + yx];
    }
}

// ---------------- fp16 m16n8k16 implicit GEMM 3x3 conv (NHWC), 3-stage cp.async + ldmatrix ----------------
// Warp grid WM x WN; each warp: 2 m16 strips (M_w=32), NT = COUT/8/WN n8-tiles.
// A in smem fp16, 40-half (80B) pixel stride (conflict-free for ldmatrix).
// MINB: min blocks per SM (per-kernel occupancy bound).
template<int CIN, int COUT, int H, int W, int WM, int WN, int MINB>
__global__ __launch_bounds__(256, MINB) void conv_mma(const __half* __restrict__ in,
                                                      const __half* __restrict__ bpk,
                                                      const float* __restrict__ bias,
                                                      float* __restrict__ out,
                                                      double* __restrict__ dsum,
                                                      double* __restrict__ dsumsq)
{
    constexpr int HW = H * W;
    constexpr int LHW = (HW == 1024) ? 10 : (HW == 256) ? 8 : 6;
    constexpr int LW  = (W == 32) ? 5 : (W == 16) ? 4 : 3;
    constexpr int CCH = CIN / 32;
    constexpr int NCH = 9 * CCH;
    constexpr int PX = WM * 32;
    constexpr int NTILE = COUT / 8;
    constexpr int NT = NTILE / WN;
    constexpr uint32_t A_BYTES = PX * 80;          // 40 halves per pixel
    constexpr uint32_t B_BYTES = 128 * COUT;       // hi+lo, 32 k-halves
    constexpr int NA = PX * 4 / 256;               // A cp.asyncs per thread
    constexpr int NB = (B_BYTES / 16) / 256;       // B cp.asyncs per thread

    extern __shared__ char smem[];
    float* Ss = (float*)(smem + 3 * A_BYTES + 3 * B_BYTES);   // [2*COUT]
    const uint32_t sA = smem_u32(smem);
    const uint32_t sB = sA + 3 * A_BYTES;

    const int tid  = threadIdx.x;
    const int wid  = tid >> 5;
    const int lane = tid & 31;
    const int g = lane >> 2, t = lane & 3;
    const int wm = wid % WM, wn = wid / WM;
    const int p0 = blockIdx.x * PX;

    if (tid < 2 * COUT) Ss[tid] = 0.f;

    // issue a chunk's A (im2col gather, coords recomputed: shifts only) + B (linear)
    auto issue = [&](int ch, int buf) {
        int tap = ch / CCH, c32 = ch % CCH;
        int ky = tap / 3 - 1, kx = tap % 3 - 1;
        uint32_t ab = sA + (uint32_t)buf * A_BYTES;
        const int j4 = tid & 3;
        #pragma unroll
        for (int it = 0; it < NA; it++) {
            int lin = it * 256 + tid;
            int ml = lin >> 2;
            int P = p0 + ml;
            int img = P >> LHW, pix = P & (HW - 1);
            int yy = (pix >> LW) + ky, xx = (pix & (W - 1)) + kx;
            bool ok = ((unsigned)yy < (unsigned)H) && ((unsigned)xx < (unsigned)W);
            const __half* gp = in + (size_t)img * HW * CIN + j4 * 8
                             + (ok ? ((size_t)((yy << LW) + xx) * CIN + c32 * 32) : 0);
            cp_async16(ab + (uint32_t)(ml * 80 + j4 * 16), gp, ok);
        }
        const uint4* src = (const uint4*)(bpk + (size_t)ch * (B_BYTES / 2));
        uint32_t bb = sB + (uint32_t)buf * B_BYTES;
        #pragma unroll
        for (int i = 0; i < NB; i++) {
            int e = i * 256 + tid;
            cp_async16(bb + (uint32_t)e * 16, src + e, true);
        }
        cp_commit();
    };

    float accH[NT][2][4], accL[NT][2][4];
    #pragma unroll
    for (int j = 0; j < NT; j++)
        #pragma unroll
        for (int ms = 0; ms < 2; ms++)
            #pragma unroll
            for (int q = 0; q < 4; q++) { accH[j][ms][q] = 0.f; accL[j][ms][q] = 0.f; }

    issue(0, 0);
    if (NCH > 1) issue(1, 1);

    // ldmatrix lane addressing (within A buffer):
    const int m0 = wm * 32;
    const uint32_t lrow = (uint32_t)(m0 + (lane & 7) + (((lane >> 3) & 1) << 3));
    const uint32_t lkoff = (uint32_t)((lane >> 4) << 4);

    for (int ch = 0; ch < NCH; ch++) {
        int buf = ch % 3;
        if (ch + 2 < NCH)      { issue(ch + 2, (ch + 2) % 3); cp_wait2(); }
        else if (ch + 1 < NCH) { cp_wait1(); }
        else                   { cp_wait0(); }
        __syncthreads();

        const uint32_t abase = sA + (uint32_t)buf * A_BYTES;
        const uint4* Bs4 = (const uint4*)(smem + 3 * A_BYTES + (uint32_t)buf * B_BYTES);
        #pragma unroll
        for (int s = 0; s < 2; s++) {
            uint32_t a[2][4];
            #pragma unroll
            for (int ms = 0; ms < 2; ms++) {
                uint32_t addr = abase + (lrow + ms * 16) * 80 + s * 32 + lkoff;
                ldsm4(a[ms][0], a[ms][1], a[ms][2], a[ms][3], addr);
            }
            #pragma unroll
            for (int j = 0; j < NT; j++) {
                int jg = wn * NT + j;
                uint4 bf = Bs4[(s * NTILE + jg) * 32 + lane];
                #pragma unroll
                for (int ms = 0; ms < 2; ms++) {
                    asm("mma.sync.aligned.m16n8k16.row.col.f32.f16.f16.f32 "
                        "{%0,%1,%2,%3}, {%4,%5,%6,%7}, {%8,%9}, {%0,%1,%2,%3};"
                        : "+f"(accH[j][ms][0]), "+f"(accH[j][ms][1]), "+f"(accH[j][ms][2]), "+f"(accH[j][ms][3])
                        : "r"(a[ms][0]), "r"(a[ms][1]), "r"(a[ms][2]), "r"(a[ms][3]), "r"(bf.x), "r"(bf.y));
                    asm("mma.sync.aligned.m16n8k16.row.col.f32.f16.f16.f32 "
                        "{%0,%1,%2,%3}, {%4,%5,%6,%7}, {%8,%9}, {%0,%1,%2,%3};"
                        : "+f"(accL[j][ms][0]), "+f"(accL[j][ms][1]), "+f"(accL[j][ms][2]), "+f"(accL[j][ms][3])
                        : "r"(a[ms][0]), "r"(a[ms][1]), "r"(a[ms][2]), "r"(a[ms][3]), "r"(bf.z), "r"(bf.w));
                }
            }
        }
        __syncthreads();
    }

    // ---- epilogue: combine hi + lo*2^-11, bias, store (NHWC), fused BN stats ----
    const float LS = 1.0f / 2048.0f;
    #pragma unroll
    for (int j = 0; j < NT; j++) {
        int col = (wn * NT + j) * 8 + 2 * t;
        float2 bb = *(const float2*)&bias[col];
        float s0 = 0.f, s1 = 0.f, q0 = 0.f, q1 = 0.f;
        #pragma unroll
        for (int ms = 0; ms < 2; ms++) {
            int row0 = p0 + m0 + ms * 16 + g;
            float2 v0 = make_float2(accH[j][ms][0] + accL[j][ms][0] * LS + bb.x,
                                    accH[j][ms][1] + accL[j][ms][1] * LS + bb.y);
            float2 v1 = make_float2(accH[j][ms][2] + accL[j][ms][2] * LS + bb.x,
                                    accH[j][ms][3] + accL[j][ms][3] * LS + bb.y);
            *(float2*)&out[(size_t)row0 * COUT + col] = v0;
            *(float2*)&out[(size_t)(row0 + 8) * COUT + col] = v1;
            s0 += v0.x + v1.x; s1 += v0.y + v1.y;
            q0 += v0.x * v0.x + v1.x * v1.x;
            q1 += v0.y * v0.y + v1.y * v1.y;
        }
        #pragma unroll
        for (int off = 4; off < 32; off <<= 1) {
            s0 += __shfl_xor_sync(0xffffffffu, s0, off);
            s1 += __shfl_xor_sync(0xffffffffu, s1, off);
            q0 += __shfl_xor_sync(0xffffffffu, q0, off);
            q1 += __shfl_xor_sync(0xffffffffu, q1, off);
        }
        if (g == 0) {
            atomicAdd(&Ss[col], s0);
            atomicAdd(&Ss[col + 1], s1);
            atomicAdd(&Ss[COUT + col], q0);
            atomicAdd(&Ss[COUT + col + 1], q1);
        }
    }
    __syncthreads();
    if (tid < COUT) {
        atomicAdd(&dsum[tid], (double)Ss[tid]);
        atomicAdd(&dsumsq[tid], (double)Ss[COUT + tid]);
    }
}

// ---------------- layer-1 direct fp32 conv (CIN=3), NCHW in -> NHWC out, fused BN stats ----------------
template<int CIN, int COUT, int H, int W, int RPB, int CO_BLK, int CCH, int NT>
__global__ __launch_bounds__(NT) void conv3x3_kernel(
    const float* __restrict__ in, const float* __restrict__ wgt,
    const float* __restrict__ bias, float* __restrict__ out,
    double* __restrict__ dsum, double* __restrict__ dsumsq)
{
    constexpr int TH = RPB + 2, TW = W + 2;
    constexpr int IN_FLOATS = CCH * TH * TW;
    constexpr int W_FLOATS = CCH * 9 * CO_BLK;
    constexpr int NCG = CO_BLK / 8;
    extern __shared__ float smemf[];
    float* s_in = smemf;
    float* s_w  = smemf + IN_FLOATS;
    float* Ss   = smemf + IN_FLOATS + W_FLOATS;

    const int m = blockIdx.x;
    const int row0 = blockIdx.y * RPB;
    const int cobase = blockIdx.z * CO_BLK;
    const int tid = threadIdx.x;
    const int lane = tid & 31;
    const int cg = tid % NCG;
    const int pg = tid / NCG;
    const int r = pg / (W / 4);
    const int c0 = (pg % (W / 4)) * 4;

    if (tid < 2 * COUT) Ss[tid] = 0.f;

    float acc[4][8];
    #pragma unroll
    for (int p = 0; p < 4; p++)
        #pragma unroll
        for (int q = 0; q < 8; q++) acc[p][q] = 0.f;

    for (int cb = 0; cb < CIN; cb += CCH) {
        for (int e = tid; e < IN_FLOATS; e += NT) {
            int ci = e / (TH * TW); int rem = e % (TH * TW);
            int rr = rem / TW, cc = rem % TW;
            int gr = row0 - 1 + rr, gc = cc - 1;
            float v = 0.f;
            if (gr >= 0 && gr < H && gc >= 0 && gc < W)
                v = in[(((size_t)m * CIN + cb + ci) * H + gr) * W + gc];
            s_in[e] = v;
        }
        for (int e = tid; e < W_FLOATS; e += NT) {
            int co = e % CO_BLK; int t9 = (e / CO_BLK) % 9; int ci = e / (9 * CO_BLK);
            s_w[e] = wgt[(((size_t)(cobase + co)) * CIN + cb + ci) * 9 + t9];
        }
        __syncthreads();

        for (int ci = 0; ci < CCH; ci++) {
            const float* tin = s_in + ci * TH * TW;
            const float* tw  = s_w  + ci * 9 * CO_BLK + cg * 8;
            #pragma unroll
            for (int kh = 0; kh < 3; kh++) {
                float xv[6];
                const float* rowp = tin + (r + kh) * TW + c0;
                #pragma unroll
                for (int j = 0; j < 6; j++) xv[j] = rowp[j];
                #pragma unroll
                for (int kw = 0; kw < 3; kw++) {
                    const float4 w0 = *(const float4*)(tw + (kh * 3 + kw) * CO_BLK);
                    const float4 w1 = *(const float4*)(tw + (kh * 3 + kw) * CO_BLK + 4);
                    float wv[8] = {w0.x, w0.y, w0.z, w0.w, w1.x, w1.y, w1.z, w1.w};
                    #pragma unroll
                    for (int p = 0; p < 4; p++)
                        #pragma unroll
                        for (int q = 0; q < 8; q++)
                            acc[p][q] += xv[kw + p] * wv[q];
                }
            }
        }
        __syncthreads();
    }

    float bq[8];
    #pragma unroll
    for (int q = 0; q < 8; q++) bq[q] = bias[cobase + cg * 8 + q];
    float ssum[8], ssq[8];
    #pragma unroll
    for (int q = 0; q < 8; q++) { ssum[q] = 0.f; ssq[q] = 0.f; }
    #pragma unroll
    for (int p = 0; p < 4; p++) {
        float v[8];
        #pragma unroll
        for (int q = 0; q < 8; q++) {
            v[q] = acc[p][q] + bq[q];
            ssum[q] += v[q];
            ssq[q]  += v[q] * v[q];
        }
        float* op = &out[(((size_t)m * H + row0 + r) * W + c0 + p) * COUT + cobase + cg * 8];
        *(float4*)op       = make_float4(v[0], v[1], v[2], v[3]);
        *(float4*)(op + 4) = make_float4(v[4], v[5], v[6], v[7]);
    }
    #pragma unroll
    for (int off = 4; off < 32; off <<= 1)
        #pragma unroll
        for (int q = 0; q < 8; q++) {
            ssum[q] += __shfl_xor_sync(0xffffffffu, ssum[q], off);
            ssq[q]  += __shfl_xor_sync(0xffffffffu, ssq[q], off);
        }
    if (lane < 4) {
        #pragma unroll
        for (int q = 0; q < 8; q++) {
            int chn = cobase + lane * 8 + q;
            atomicAdd(&Ss[chn], ssum[q]);
            atomicAdd(&Ss[COUT + chn], ssq[q]);
        }
    }
    __syncthreads();
    if (tid < COUT) {
        atomicAdd(&dsum[tid], (double)Ss[tid]);
        atomicAdd(&dsumsq[tid], (double)Ss[COUT + tid]);
    }
}

// ---------------- inline BN finalize helper ----------------
__device__ __forceinline__ void bn_coeffs(const double* sum, const double* sumsq, double icnt,
                                          const float* gam, const float* bet, int c,
                                          float& iv, float& sh)
{
    double mu = sum[c] * icnt;
    double var = sumsq[c] * icnt - mu * mu;
    iv = gam[c] / sqrtf((float)var + 1e-5f);
    sh = bet[c] - (float)mu * iv;
}

// ---------------- LIF (TAU=2, th=1, hard reset), NHWC, fp16 spikes out ----------------
__global__ void lif_seq_kernel(const float* __restrict__ x, __half* __restrict__ s,
                               const double* __restrict__ sum, const double* __restrict__ sumsq,
                               double icnt, const float* __restrict__ gam, const float* __restrict__ bet,
                               int nsite, int C)
{
    int idx = blockIdx.x * blockDim.x + threadIdx.x;
    if (idx >= nsite) return;
    float iv = 1.f, sh = 0.f;
    if (gam) bn_coeffs(sum, sumsq, icnt, gam, bet, idx % C, iv, sh);
    float v = 0.f;
    #pragma unroll
    for (int t = 0; t < 8; t++) {
        float y = x[(size_t)t * nsite + idx] * iv + sh;
        v = 0.5f * (v + y);
        float sp = (v >= 1.0f) ? 1.0f : 0.0f;
        s[(size_t)t * nsite + idx] = __float2half(sp);
        v *= (1.0f - sp);
    }
}

// Layer-1 LIF: input identical across T (read once)
__global__ void lif_bcast_kernel(const float* __restrict__ x, __half* __restrict__ s,
                                 const double* __restrict__ sum, const double* __restrict__ sumsq,
                                 double icnt, const float* __restrict__ gam, const float* __restrict__ bet,
                                 int nsite, int C)
{
    int idx = blockIdx.x * blockDim.x + threadIdx.x;
    if (idx >= nsite) return;
    float iv, sh;
    bn_coeffs(sum, sumsq, icnt, gam, bet, idx % C, iv, sh);
    float y = x[idx] * iv + sh;
    float v = 0.f;
    #pragma unroll
    for (int t = 0; t < 8; t++) {
        v = 0.5f * (v + y);
        float sp = (v >= 1.0f) ? 1.0f : 0.0f;
        s[(size_t)t * nsite + idx] = __float2half(sp);
        v *= (1.0f - sp);
    }
}

// ---------------- LIF + 2x2 maxpool fused, fp16 spikes out ----------------
__global__ void lif_pool_kernel(const float* __restrict__ x, __half* __restrict__ s,
                                const double* __restrict__ sum, const double* __restrict__ sumsq,
                                double icnt, const float* __restrict__ gam, const float* __restrict__ bet,
                                int nout, int C, int OH, int OW, int Nimg)
{
    int idx = blockIdx.x * blockDim.x + threadIdx.x;
    if (idx >= nout) return;
    int c = idx % C;
    int r = idx / C;
    int ox = r % OW; r /= OW;
    int oy = r % OH;
    int n = r / OH;
    float iv, sh;
    bn_coeffs(sum, sumsq, icnt, gam, bet, c, iv, sh);
    int Wi = OW * 2, Hi = OH * 2;
    size_t base = (((size_t)n * Hi + 2 * oy) * Wi + 2 * ox) * C + c;
    size_t tstr = (size_t)Nimg * Hi * Wi * C;
    size_t rstr = (size_t)Wi * C;
    float v0 = 0.f, v1 = 0.f, v2 = 0.f, v3 = 0.f;
    #pragma unroll
    for (int t = 0; t < 8; t++) {
        const float* p = x + (size_t)t * tstr + base;
        float y0 = p[0] * iv + sh;
        float y1 = p[C] * iv + sh;
        float y2 = p[rstr] * iv + sh;
        float y3 = p[rstr + C] * iv + sh;
        v0 = 0.5f * (v0 + y0); float s0 = (v0 >= 1.0f) ? 1.0f : 0.0f; v0 *= (1.0f - s0);
        v1 = 0.5f * (v1 + y1); float s1 = (v1 >= 1.0f) ? 1.0f : 0.0f; v1 *= (1.0f - s1);
        v2 = 0.5f * (v2 + y2); float s2 = (v2 >= 1.0f) ? 1.0f : 0.0f; v2 *= (1.0f - s2);
        v3 = 0.5f * (v3 + y3); float s3 = (v3 >= 1.0f) ? 1.0f : 0.0f; v3 *= (1.0f - s3);
        s[(size_t)t * nout + idx] = __float2half(fmaxf(fmaxf(s0, s1), fmaxf(s2, s3)));
    }
}

// ---------------- fc1: [1024,2048](fp16 spikes) x [128,2048]^T + bias ----------------
__global__ __launch_bounds__(256) void fc1_kernel(const __half* __restrict__ A,
                                                  const float* __restrict__ Bw,
                                                  const float* __restrict__ bias,
                                                  float* __restrict__ C)
{
    __shared__ float As[32][64];
    __shared__ float Bs[64][132];
    int tid = threadIdx.x;
    int r0 = blockIdx.x * 32;
    int tx = tid % 32, ty = tid / 32;
    float acc[4][4];
    #pragma unroll
    for (int i = 0; i < 4; i++)
        #pragma unroll
        for (int j = 0; j < 4; j++) acc[i][j] = 0.f;

    for (int k0 = 0; k0 < 2048; k0 += 64) {
        #pragma unroll
        for (int l = 0; l < 8; l++) {
            int e = tid + l * 256;
            int rr = e >> 6, kk = e & 63;
            As[rr][kk] = __half2float(A[(size_t)(r0 + rr) * 2048 + k0 + kk]);
        }
        #pragma unroll
        for (int l = 0; l < 32; l++) {
            int e = tid + l * 256;
            int kk = e & 63, oo = e >> 6;
            Bs[kk][oo] = Bw[(size_t)oo * 2048 + k0 + kk];
        }
        __syncthreads();
        for (int kk = 0; kk < 64; kk++) {
            float a[4];
            #pragma unroll
            for (int i = 0; i < 4; i++) a[i] = As[ty * 4 + i][kk];
            float4 bv = *(const float4*)&Bs[kk][tx * 4];
            float b[4] = {bv.x, bv.y, bv.z, bv.w};
            #pragma unroll
            for (int i = 0; i < 4; i++)
                #pragma unroll
                for (int j = 0; j < 4; j++)
                    acc[i][j] += a[i] * b[j];
        }
        __syncthreads();
    }
    #pragma unroll
    for (int i = 0; i < 4; i++)
        #pragma unroll
        for (int j = 0; j < 4; j++)
            C[(size_t)(r0 + ty * 4 + i) * 128 + tx * 4 + j] = acc[i][j] + bias[tx * 4 + j];
}

// ---------------- fc2 + LIF + mean over T, fused (fp16 h) ----------------
__global__ __launch_bounds__(320) void fc2_lif_mean_kernel(const __half* __restrict__ h,
                                                           const float* __restrict__ w2,
                                                           const float* __restrict__ b2,
                                                           float* __restrict__ out)
{
    int n = blockIdx.x;
    int o = threadIdx.x / 32;
    int lane = threadIdx.x % 32;
    float w[4];
    #pragma unroll
    for (int j = 0; j < 4; j++) w[j] = w2[o * 128 + lane * 4 + j];
    float bb = b2[o];
    float v = 0.f, accum = 0.f;
    #pragma unroll
    for (int t = 0; t < 8; t++) {
        const __half* hp = h + (size_t)t * 16384 + (size_t)n * 128 + lane * 4;
        float p = 0.f;
        #pragma unroll
        for (int j = 0; j < 4; j++) p += __half2float(hp[j]) * w[j];
        #pragma unroll
        for (int off = 16; off > 0; off >>= 1)
            p += __shfl_xor_sync(0xffffffffu, p, off);
        float y = p + bb;
        v = 0.5f * (v + y);
        float sp = (v >= 1.0f) ? 1.0f : 0.0f;
        v *= (1.0f - sp);
        accum += sp;
    }
    if (lane == 0) out[n * 10 + o] = accum * 0.125f;
}

// ---------------- host orchestration ----------------
extern "C" void kernel_launch(void* const* d_in, const int* in_sizes, int n_in,
                              void* d_out, int out_size)
{
    const float* x = (const float*)d_in[0];
    const float* w[6]; const float* b[6]; const float* gm[6]; const float* be[6];
    for (int i = 0; i < 6; i++) {
        w[i]  = (const float*)d_in[1 + 4 * i];
        b[i]  = (const float*)d_in[2 + 4 * i];
        gm[i] = (const float*)d_in[3 + 4 * i];
        be[i] = (const float*)d_in[4 + 4 * i];
    }
    const float* fc1_w = (const float*)d_in[25];
    const float* fc1_b = (const float*)d_in[26];
    const float* fc2_w = (const float*)d_in[27];
    const float* fc2_b = (const float*)d_in[28];
    float* out = (float*)d_out;

    float *bufA_f, *bufB_f, *conv, *wpk;
    double *sum, *sumsq;
    cudaGetSymbolAddress((void**)&bufA_f, g_bufA);
    cudaGetSymbolAddress((void**)&bufB_f, g_bufB);
    cudaGetSymbolAddress((void**)&conv, g_conv);
    cudaGetSymbolAddress((void**)&wpk, g_wpk);
    cudaGetSymbolAddress((void**)&sum, g_sum);
    cudaGetSymbolAddress((void**)&sumsq, g_sumsq);
    __half* bufA = (__half*)bufA_f;
    __half* bufB = (__half*)bufB_f;

    __half* hk = (__half*)wpk;
    __half* wp2 = hk;             // halves
    __half* wp3 = hk + 18432;
    __half* wp4 = hk + 55296;
    __half* wp5 = hk + 129024;
    __half* wp6 = hk + 276480;
    float*  wfc = wpk + 300000;   // floats

    auto k1 = conv3x3_kernel<3, 32, 32, 32, 8, 32, 3, 256>;
    const int sm1 = (3 * 10 * 34 + 3 * 9 * 32 + 64) * 4;

    auto g2 = conv_mma<32, 32, 32, 32, 4, 2, 3>;   // PX=128, NT=2, minocc 3
    auto g3 = conv_mma<32, 64, 16, 16, 4, 2, 2>;   // PX=128, NT=4, minocc 2
    auto g4 = conv_mma<64, 64, 16, 16, 4, 2, 2>;
    auto g5 = conv_mma<64, 128, 8, 8, 2, 4, 2>;    // PX=64, NT=4, minocc 2
    auto g6 = conv_mma<128, 128, 8, 8, 2, 4, 2>;
    const int smg2  = 3 * 128 * 80 + 3 * 128 * 32 + 64 * 4;     // 43264
    const int smg34 = 3 * 128 * 80 + 3 * 128 * 64 + 128 * 4;    // 55808
    const int smg56 = 3 * 64 * 80 + 3 * 128 * 128 + 256 * 4;    // 65536
    cudaFuncSetAttribute((const void*)g2, cudaFuncAttributeMaxDynamicSharedMemorySize, smg2);
    cudaFuncSetAttribute((const void*)g3, cudaFuncAttributeMaxDynamicSharedMemorySize, smg34);
    cudaFuncSetAttribute((const void*)g4, cudaFuncAttributeMaxDynamicSharedMemorySize, smg34);
    cudaFuncSetAttribute((const void*)g5, cudaFuncAttributeMaxDynamicSharedMemorySize, smg56);
    cudaFuncSetAttribute((const void*)g6, cudaFuncAttributeMaxDynamicSharedMemorySize, smg56);

    const int N = 128, M = 1024;  // M = T*N
    double* s1 = sum;        double* q1 = sumsq;
    double* s2 = sum + 128;  double* q2 = sumsq + 128;
    double* s3 = sum + 256;  double* q3 = sumsq + 256;
    double* s4 = sum + 384;  double* q4 = sumsq + 384;
    double* s5 = sum + 512;  double* q5 = sumsq + 512;
    double* s6 = sum + 640;  double* q6 = sumsq + 640;

    // launch 0: prep
    prep_kernel<<<3257, 256>>>(w[1], w[2], w[3], w[4], w[5], fc1_w, wpk, sum, sumsq);
    // launch 1: layer-1 conv + fused BN stats
    k1<<<dim3(N, 4, 1), 256, sm1>>>(x, w[0], b[0], conv, s1, q1);
    // launch 2: layer-1 LIF (broadcast over T)
    {
        int nsite = N * 1024 * 32;
        lif_bcast_kernel<<<(nsite + 255) / 256, 256>>>(conv, bufA, s1, q1,
            1.0 / ((double)N * 1024), gm[0], be[0], nsite, 32);
    }
    // launch 3: layer-2 conv  <-- ncu capture target
    g2<<<M * 1024 / 128, 256, smg2>>>(bufA, wp2, b[1], conv, s2, q2);
    {
        int nout = N * 16 * 16 * 32;
        lif_pool_kernel<<<(nout + 255) / 256, 256>>>(conv, bufB, s2, q2,
            1.0 / ((double)M * 1024), gm[1], be[1], nout, 32, 16, 16, N);
    }
    // layer 3
    g3<<<M * 256 / 128, 256, smg34>>>(bufB, wp3, b[2], conv, s3, q3);
    {
        int nsite = N * 256 * 64;
        lif_seq_kernel<<<(nsite + 255) / 256, 256>>>(conv, bufA, s3, q3,
            1.0 / ((double)M * 256), gm[2], be[2], nsite, 64);
    }
    // layer 4 (+pool)
    g4<<<M * 256 / 128, 256, smg34>>>(bufA, wp4, b[3], conv, s4, q4);
    {
        int nout = N * 8 * 8 * 64;
        lif_pool_kernel<<<(nout + 255) / 256, 256>>>(conv, bufB, s4, q4,
            1.0 / ((double)M * 256), gm[3], be[3], nout, 64, 8, 8, N);
    }
    // layer 5
    g5<<<M * 64 / 64, 256, smg56>>>(bufB, wp5, b[4], conv, s5, q5);
    {
        int nsite = N * 64 * 128;
        lif_seq_kernel<<<(nsite + 255) / 256, 256>>>(conv, bufA, s5, q5,
            1.0 / ((double)M * 64), gm[4], be[4], nsite, 128);
    }
    // layer 6 (+pool)
    g6<<<M * 64 / 64, 256, smg56>>>(bufA, wp6, b[5], conv, s6, q6);
    {
        int nout = N * 4 * 4 * 128;
        lif_pool_kernel<<<(nout + 255) / 256, 256>>>(conv, bufB, s6, q6,
            1.0 / ((double)M * 64), gm[5], be[5], nout, 128, 4, 4, N);
    }
    // fc1 + LIF
    fc1_kernel<<<32, 256>>>(bufB, wfc, fc1_b, conv);
    {
        int nsite = N * 128;
        lif_seq_kernel<<<(nsite + 255) / 256, 256>>>(conv, bufA, (const double*)0, (const double*)0,
            0.0, (const float*)0, (const float*)0, nsite, 1);
    }
    // fc2 + LIF + mean
    fc2_lif_mean_kernel<<<N, 320>>>(bufA, fc2_w, fc2_b, out);
}